// round 12
// baseline (speedup 1.0000x reference)
#include <cuda_runtime.h>

// GRU -> LSTM -> FC fused recurrent kernel.
// Warp-specialized DECOUPLED pipeline: producer (GRU + LSTM input-proj row2)
// and consumer (LSTM rest + gates + FC) communicate through 16-deep rings
// with split named barriers (bar.arrive / bar.sync) instead of lockstep
// bar.sync. Producer may run up to 11 iterations ahead; jitter is absorbed.
// 2 sequences per block, B=1024 (512 blocks), T=1024, H=18, MUFU.TANH gates.

#define Hh 18
#define Tt 1024
#define NB 512
#define RING 16

typedef unsigned long long ull;

__device__ __forceinline__ void fma2(ull &d, ull a, ull b) {
    asm("fma.rn.f32x2 %0, %1, %2, %0;" : "+l"(d) : "l"(a), "l"(b));
}
__device__ __forceinline__ float hadd2(ull v) {
    float lo, hi;
    asm("mov.b64 {%0,%1}, %2;" : "=f"(lo), "=f"(hi) : "l"(v));
    return lo + hi;
}
__device__ __forceinline__ float tanh_fast(float x) {
    float y;
    asm("tanh.approx.f32 %0, %1;" : "=f"(y) : "f"(x));
    return y;
}
__device__ __forceinline__ float sigf(float x) {          // 0.5+0.5*tanh(x/2)
    return fmaf(0.5f, tanh_fast(0.5f * x), 0.5f);
}
__device__ __forceinline__ float tanhf_(float x) { return tanh_fast(x); }

__device__ __forceinline__ void bar_sync_1()   { asm volatile("bar.sync 1, 64;"   ::: "memory"); }
__device__ __forceinline__ void bar_arrive_1() { asm volatile("bar.arrive 1, 64;" ::: "memory"); }
__device__ __forceinline__ void bar_sync_2()   { asm volatile("bar.sync 2, 64;"   ::: "memory"); }
__device__ __forceinline__ void bar_arrive_2() { asm volatile("bar.arrive 2, 64;" ::: "memory"); }
__device__ __forceinline__ void membar_cta()   { asm volatile("membar.cta;"       ::: "memory"); }

__global__ __launch_bounds__(64) void gru_lstm_decoupled(
    const float* __restrict__ x,
    const float* __restrict__ gWih, const float* __restrict__ gWhh,
    const float* __restrict__ gbih, const float* __restrict__ gbhh,
    const float* __restrict__ lWih, const float* __restrict__ lWhh,
    const float* __restrict__ lbih, const float* __restrict__ lbhh,
    const float* __restrict__ fcW, const float* __restrict__ fcb,
    float* __restrict__ out)
{
    const int tid = threadIdx.x;
    const int w   = tid >> 5;
    const int j   = tid & 31;
    const int b0  = 2 * blockIdx.x;

    // producer-local
    __shared__ __align__(16) float sx[2][Hh];
    __shared__ __align__(16) float shg[2][Hh];
    __shared__ __align__(16) float sxi[2][54];
    __shared__ __align__(16) float shh[2][54];
    // producer -> consumer rings (16 deep)
    __shared__ __align__(16) float sg[RING][2][Hh];    // GRU outputs
    __shared__ __align__(16) float sl2[RING][2][24];   // LSTM row-2 input-proj
    // consumer-local
    __shared__ __align__(16) float shl[2][Hh];
    __shared__ __align__(16) float sl[2][72];
    __shared__ __align__(16) float hist[2][32][Hh];

    if (w == 0) {
        // ======== PRODUCER: GRU + LSTM input-proj row set 2 ========
        ull wgx[2][9], wgh[2][9], wlx2[9];
        float bgx[2], bgh[2];
        if (j < 27) {
            #pragma unroll
            for (int r = 0; r < 2; r++) {
                const int row = 2 * j + r;
                const ull* pi = (const ull*)(gWih + row * Hh);
                const ull* ph = (const ull*)(gWhh + row * Hh);
                #pragma unroll
                for (int k = 0; k < 9; k++) { wgx[r][k] = pi[k]; wgh[r][k] = ph[k]; }
                bgx[r] = gbih[row];
                bgh[r] = gbhh[row];
            }
        }
        if (j < 24) {
            const ull* p2 = (const ull*)(lWih + (3 * j + 2) * Hh);
            #pragma unroll
            for (int k = 0; k < 9; k++) wlx2[k] = p2[k];
        }
        if (j < Hh) { shg[0][j] = 0.f; shg[1][j] = 0.f; }
        float hg0 = 0.f, hg1 = 0.f;

        const float* xb0 = x + (size_t)b0 * Tt * Hh;
        const float* xb1 = xb0 + (size_t)Tt * Hh;
        float xv0 = (j < Hh) ? xb0[j] : 0.f;
        float xv1 = (j < Hh) ? xb1[j] : 0.f;

        #pragma unroll 1
        for (int t = 0; t < Tt; t++) {
            // amortized backpressure: at t=12,16,...,1020 wait for consumer
            // arrival #m (issued after consumer finished step 4m-1)
            if (t >= 12 && (t & 3) == 0) bar_sync_2();

            if (j < Hh) { sx[0][j] = xv0; sx[1][j] = xv1; }
            float xn0 = 0.f, xn1 = 0.f;
            if (j < Hh && t + 1 < Tt) {
                xn0 = xb0[(size_t)(t + 1) * Hh + j];
                xn1 = xb1[(size_t)(t + 1) * Hh + j];
            }
            __syncwarp();

            if (j < 27) {
                ull a00=0, a01=0, h00=0, h01=0, a10=0, a11=0, h10=0, h11=0;
                const ull* px0 = (const ull*)sx[0];
                const ull* px1 = (const ull*)sx[1];
                const ull* ph0 = (const ull*)shg[0];
                const ull* ph1 = (const ull*)shg[1];
                #pragma unroll
                for (int k = 0; k < 9; k++) {
                    const ull x0k = px0[k], h0k = ph0[k];
                    const ull x1k = px1[k], h1k = ph1[k];
                    fma2(a00, wgx[0][k], x0k); fma2(h00, wgh[0][k], h0k);
                    fma2(a01, wgx[1][k], x0k); fma2(h01, wgh[1][k], h0k);
                    fma2(a10, wgx[0][k], x1k); fma2(h10, wgh[0][k], h1k);
                    fma2(a11, wgx[1][k], x1k); fma2(h11, wgh[1][k], h1k);
                }
                sxi[0][2*j]   = hadd2(a00) + bgx[0];
                sxi[0][2*j+1] = hadd2(a01) + bgx[1];
                shh[0][2*j]   = hadd2(h00) + bgh[0];
                shh[0][2*j+1] = hadd2(h01) + bgh[1];
                sxi[1][2*j]   = hadd2(a10) + bgx[0];
                sxi[1][2*j+1] = hadd2(a11) + bgx[1];
                shh[1][2*j]   = hadd2(h10) + bgh[0];
                shh[1][2*j+1] = hadd2(h11) + bgh[1];
            }
            __syncwarp();

            if (j < Hh) {
                const float r0 = sigf(sxi[0][j]      + shh[0][j]);
                const float r1 = sigf(sxi[1][j]      + shh[1][j]);
                const float z0 = sigf(sxi[0][18 + j] + shh[0][18 + j]);
                const float z1 = sigf(sxi[1][18 + j] + shh[1][18 + j]);
                const float n0 = tanhf_(fmaf(r0, shh[0][36 + j], sxi[0][36 + j]));
                const float n1 = tanhf_(fmaf(r1, shh[1][36 + j], sxi[1][36 + j]));
                hg0 = fmaf(z0, hg0 - n0, n0);
                hg1 = fmaf(z1, hg1 - n1, n1);
                shg[0][j] = hg0;  sg[t & (RING-1)][0][j] = hg0;
                shg[1][j] = hg1;  sg[t & (RING-1)][1][j] = hg1;
            }
            __syncwarp();

            // LSTM input-projection for row set 2 (rebalances fma issue)
            if (j < 24) {
                ull A20 = 0, A21 = 0;
                const ull* pg0 = (const ull*)shg[0];
                const ull* pg1 = (const ull*)shg[1];
                #pragma unroll
                for (int k = 0; k < 9; k++) {
                    fma2(A20, wlx2[k], pg0[k]);
                    fma2(A21, wlx2[k], pg1[k]);
                }
                sl2[t & (RING-1)][0][j] = hadd2(A20);
                sl2[t & (RING-1)][1][j] = hadd2(A21);
            }

            membar_cta();     // bar.arrive has no memory ordering; fence first
            bar_arrive_1();   // signal step t published

            xv0 = xn0; xv1 = xn1;
        }
    } else {
        // ======== CONSUMER: LSTM (rows 0,1 in-proj + all recurrent) + FC ====
        ull wlxA[2][9], wlh[3][9];
        float bl[3];
        if (j < 24) {
            #pragma unroll
            for (int r = 0; r < 3; r++) {
                const int row = 3 * j + r;
                const ull* ph = (const ull*)(lWhh + row * Hh);
                #pragma unroll
                for (int k = 0; k < 9; k++) wlh[r][k] = ph[k];
                bl[r] = lbih[row] + lbhh[row];
            }
            #pragma unroll
            for (int r = 0; r < 2; r++) {
                const ull* pi = (const ull*)(lWih + (3 * j + r) * Hh);
                #pragma unroll
                for (int k = 0; k < 9; k++) wlxA[r][k] = pi[k];
            }
        }
        const float fw = (j < Hh) ? fcW[j] : 0.f;
        const float fb = fcb[0];
        if (j < Hh) { shl[0][j] = 0.f; shl[1][j] = 0.f; }
        __syncwarp();
        float c0 = 0.f, c1 = 0.f;

        float* ob0 = out + (size_t)b0 * Tt;
        float* ob1 = ob0 + Tt;

        #pragma unroll 1
        for (int it = 1; it <= Tt; it++) {
            const int t = it - 1;
            bar_sync_1();          // wait for producer step t (fences producer writes)

            if (j < 24) {
                const ull* pg0 = (const ull*)(sg[t & (RING-1)][0]);
                const ull* pg1 = (const ull*)(sg[t & (RING-1)][1]);
                const ull* ph0 = (const ull*)shl[0];
                const ull* ph1 = (const ull*)shl[1];
                ull A00=0, A01=0, B00=0, B01=0, B02=0;
                ull A10=0, A11=0, B10=0, B11=0, B12=0;
                #pragma unroll
                for (int k = 0; k < 9; k++) {
                    const ull g0k = pg0[k], h0k = ph0[k];
                    const ull g1k = pg1[k], h1k = ph1[k];
                    fma2(A00, wlxA[0][k], g0k); fma2(B00, wlh[0][k], h0k);
                    fma2(A01, wlxA[1][k], g0k); fma2(B01, wlh[1][k], h0k);
                    fma2(B02, wlh[2][k], h0k);
                    fma2(A10, wlxA[0][k], g1k); fma2(B10, wlh[0][k], h1k);
                    fma2(A11, wlxA[1][k], g1k); fma2(B11, wlh[1][k], h1k);
                    fma2(B12, wlh[2][k], h1k);
                }
                sl[0][3*j]   = hadd2(A00) + hadd2(B00) + bl[0];
                sl[0][3*j+1] = hadd2(A01) + hadd2(B01) + bl[1];
                sl[0][3*j+2] = sl2[t & (RING-1)][0][j] + hadd2(B02) + bl[2];
                sl[1][3*j]   = hadd2(A10) + hadd2(B10) + bl[0];
                sl[1][3*j+1] = hadd2(A11) + hadd2(B11) + bl[1];
                sl[1][3*j+2] = sl2[t & (RING-1)][1][j] + hadd2(B12) + bl[2];
            }
            __syncwarp();

            if (j < Hh) {
                const float i0 = sigf(sl[0][j]);
                const float i1 = sigf(sl[1][j]);
                const float f0 = sigf(sl[0][18 + j]);
                const float f1 = sigf(sl[1][18 + j]);
                const float g0 = tanhf_(sl[0][36 + j]);
                const float g1 = tanhf_(sl[1][36 + j]);
                const float o0 = sigf(sl[0][54 + j]);
                const float o1 = sigf(sl[1][54 + j]);
                c0 = fmaf(f0, c0, i0 * g0);
                c1 = fmaf(f1, c1, i1 * g1);
                const float hl0 = o0 * tanhf_(c0);
                const float hl1 = o1 * tanhf_(c1);
                shl[0][j] = hl0;  hist[0][t & 31][j] = hl0 * fw;
                shl[1][j] = hl1;  hist[1][t & 31][j] = hl1 * fw;
            }

            // amortized backpressure release: steps 3,7,...,1023
            if ((t & 3) == 3) bar_arrive_2();

            if ((t & 31) == 31) {
                __syncwarp();
                float v0 = fb, v1 = fb;
                const float* hr0 = hist[0][j];
                const float* hr1 = hist[1][j];
                #pragma unroll
                for (int k = 0; k < Hh; k++) { v0 += hr0[k]; v1 += hr1[k]; }
                ob0[t - 31 + j] = v0;
                ob1[t - 31 + j] = v1;
            }
        }
    }
}

extern "C" void kernel_launch(void* const* d_in, const int* in_sizes, int n_in,
                              void* d_out, int out_size)
{
    (void)in_sizes; (void)n_in; (void)out_size;
    gru_lstm_decoupled<<<NB, 64>>>(
        (const float*)d_in[0],
        (const float*)d_in[1], (const float*)d_in[2],
        (const float*)d_in[3], (const float*)d_in[4],
        (const float*)d_in[5], (const float*)d_in[6],
        (const float*)d_in[7], (const float*)d_in[8],
        (const float*)d_in[9], (const float*)d_in[10],
        (float*)d_out);
}

// round 14
// speedup vs baseline: 1.4642x; 1.4642x over previous
#include <cuda_runtime.h>

// GRU -> LSTM -> FC fused recurrent kernel, warp-specialized lockstep pipeline.
// 1 sequence per block, 1024 blocks x 64 threads, 8 blocks/SM (single wave).
// Warp 0: GRU recurrence + LSTM row-2 input projection (register balance).
// Warp 1: LSTM rows 0,1 input-proj + all recurrent rows + gates + deferred FC.
// One bar.sync per step; sg/sl2 double-buffered. MUFU.TANH gates.

#define Hh 18
#define Tt 1024
#define NB 1024

typedef unsigned long long ull;

__device__ __forceinline__ void fma2(ull &d, ull a, ull b) {
    asm("fma.rn.f32x2 %0, %1, %2, %0;" : "+l"(d) : "l"(a), "l"(b));
}
__device__ __forceinline__ float hadd2(ull v) {
    float lo, hi;
    asm("mov.b64 {%0,%1}, %2;" : "=f"(lo), "=f"(hi) : "l"(v));
    return lo + hi;
}
__device__ __forceinline__ float tanh_fast(float x) {
    float y;
    asm("tanh.approx.f32 %0, %1;" : "=f"(y) : "f"(x));
    return y;
}
__device__ __forceinline__ float sigf(float x) {          // 0.5+0.5*tanh(x/2)
    return fmaf(0.5f, tanh_fast(0.5f * x), 0.5f);
}
__device__ __forceinline__ float tanhf_(float x) { return tanh_fast(x); }
__device__ __forceinline__ void barrier64() {
    asm volatile("bar.sync 0, 64;" ::: "memory");
}

__global__ __launch_bounds__(64, 8) void gru_lstm_pipe1(
    const float* __restrict__ x,
    const float* __restrict__ gWih, const float* __restrict__ gWhh,
    const float* __restrict__ gbih, const float* __restrict__ gbhh,
    const float* __restrict__ lWih, const float* __restrict__ lWhh,
    const float* __restrict__ lbih, const float* __restrict__ lbhh,
    const float* __restrict__ fcW, const float* __restrict__ fcb,
    float* __restrict__ out)
{
    const int tid = threadIdx.x;
    const int w   = tid >> 5;     // 0 = GRU producer, 1 = LSTM consumer
    const int j   = tid & 31;
    const int b   = blockIdx.x;

    __shared__ __align__(16) float sx[Hh];        // x_t (producer)
    __shared__ __align__(16) float shg[Hh];       // GRU hidden (producer)
    __shared__ __align__(16) float sxi[54];       // GRU input-proj rows
    __shared__ __align__(16) float shh[54];       // GRU hidden-proj rows
    __shared__ __align__(16) float sg[2][Hh];     // GRU out double buffer
    __shared__ __align__(16) float sl2[2][24];    // LSTM row-2 in-proj buffer
    __shared__ __align__(16) float shl[Hh];       // LSTM hidden (consumer)
    __shared__ __align__(16) float sl[72];        // LSTM pre-activations
    __shared__ __align__(16) float hist[32][Hh];  // hl*fw history (consumer)

    if (w == 0) {
        // ============ PRODUCER: GRU + LSTM row-2 input projection ==========
        ull wgx[2][9], wgh[2][9], wlx2[9];
        float bgx[2], bgh[2];
        if (j < 27) {
            #pragma unroll
            for (int r = 0; r < 2; r++) {
                const int row = 2 * j + r;
                const ull* pi = (const ull*)(gWih + row * Hh);
                const ull* ph = (const ull*)(gWhh + row * Hh);
                #pragma unroll
                for (int k = 0; k < 9; k++) { wgx[r][k] = pi[k]; wgh[r][k] = ph[k]; }
                bgx[r] = gbih[row];
                bgh[r] = gbhh[row];
            }
        }
        if (j < 24) {
            const ull* p2 = (const ull*)(lWih + (3 * j + 2) * Hh);
            #pragma unroll
            for (int k = 0; k < 9; k++) wlx2[k] = p2[k];
        }
        if (j < Hh) shg[j] = 0.f;
        float hg = 0.f;

        const float* xb = x + (size_t)b * Tt * Hh;
        float xv = (j < Hh) ? xb[j] : 0.f;

        #pragma unroll 1
        for (int it = 0; it <= Tt; it++) {
            barrier64();
            if (it >= Tt) continue;
            const int t = it;

            if (j < Hh) sx[j] = xv;
            float xnx = 0.f;
            if (j < Hh && t + 1 < Tt) xnx = xb[(size_t)(t + 1) * Hh + j];
            __syncwarp();

            if (j < 27) {
                ull a0 = 0, a1 = 0, h0 = 0, h1 = 0;
                const ull* px = (const ull*)sx;
                const ull* ph = (const ull*)shg;
                #pragma unroll
                for (int k = 0; k < 9; k++) {
                    const ull xk = px[k], hk = ph[k];
                    fma2(a0, wgx[0][k], xk); fma2(h0, wgh[0][k], hk);
                    fma2(a1, wgx[1][k], xk); fma2(h1, wgh[1][k], hk);
                }
                sxi[2 * j]     = hadd2(a0) + bgx[0];
                sxi[2 * j + 1] = hadd2(a1) + bgx[1];
                shh[2 * j]     = hadd2(h0) + bgh[0];
                shh[2 * j + 1] = hadd2(h1) + bgh[1];
            }
            __syncwarp();

            if (j < Hh) {
                const float r = sigf(sxi[j]      + shh[j]);
                const float z = sigf(sxi[18 + j] + shh[18 + j]);
                const float n = tanhf_(fmaf(r, shh[36 + j], sxi[36 + j]));
                hg = fmaf(z, hg - n, n);
                shg[j] = hg;
                sg[t & 1][j] = hg;
            }
            __syncwarp();

            // LSTM input-projection row set 2 (register/issue balance)
            if (j < 24) {
                ull A2 = 0;
                const ull* pg = (const ull*)shg;
                #pragma unroll
                for (int k = 0; k < 9; k++) fma2(A2, wlx2[k], pg[k]);
                sl2[t & 1][j] = hadd2(A2);
            }
            xv = xnx;
            // publication ordered by the barrier at loop top of next iter
        }
    } else {
        // ============ CONSUMER: LSTM rows 0,1 + recurrents + gates + FC ====
        ull wlxA[2][9], wlh[3][9];
        float bl[3];
        if (j < 24) {
            #pragma unroll
            for (int r = 0; r < 3; r++) {
                const int row = 3 * j + r;
                const ull* ph = (const ull*)(lWhh + row * Hh);
                #pragma unroll
                for (int k = 0; k < 9; k++) wlh[r][k] = ph[k];
                bl[r] = lbih[row] + lbhh[row];
            }
            #pragma unroll
            for (int r = 0; r < 2; r++) {
                const ull* pi = (const ull*)(lWih + (3 * j + r) * Hh);
                #pragma unroll
                for (int k = 0; k < 9; k++) wlxA[r][k] = pi[k];
            }
        }
        const float fw = (j < Hh) ? fcW[j] : 0.f;
        const float fb = fcb[0];
        if (j < Hh) shl[j] = 0.f;
        float c = 0.f;

        float* ob = out + (size_t)b * Tt;

        #pragma unroll 1
        for (int it = 0; it <= Tt; it++) {
            barrier64();
            if (it == 0) continue;
            const int t = it - 1;

            if (j < 24) {
                const ull* pg = (const ull*)(sg[t & 1]);
                const ull* ph = (const ull*)shl;
                ull A0 = 0, A1 = 0, B0 = 0, B1 = 0, B2 = 0;
                #pragma unroll
                for (int k = 0; k < 9; k++) {
                    const ull gk = pg[k], hk = ph[k];
                    fma2(A0, wlxA[0][k], gk); fma2(B0, wlh[0][k], hk);
                    fma2(A1, wlxA[1][k], gk); fma2(B1, wlh[1][k], hk);
                    fma2(B2, wlh[2][k], hk);
                }
                sl[3 * j]     = hadd2(A0) + hadd2(B0) + bl[0];
                sl[3 * j + 1] = hadd2(A1) + hadd2(B1) + bl[1];
                sl[3 * j + 2] = sl2[t & 1][j] + hadd2(B2) + bl[2];
            }
            __syncwarp();

            if (j < Hh) {
                const float ig = sigf(sl[j]);
                const float fg = sigf(sl[18 + j]);
                const float gg = tanhf_(sl[36 + j]);
                const float og = sigf(sl[54 + j]);
                c = fmaf(fg, c, ig * gg);
                const float hl = og * tanhf_(c);
                shl[j] = hl;
                hist[t & 31][j] = hl * fw;
            }

            if ((t & 31) == 31) {
                __syncwarp();
                float v = fb;
                const float* hr = hist[j];
                #pragma unroll
                for (int k = 0; k < Hh; k++) v += hr[k];
                ob[t - 31 + j] = v;
            }
        }
    }
}

extern "C" void kernel_launch(void* const* d_in, const int* in_sizes, int n_in,
                              void* d_out, int out_size)
{
    (void)in_sizes; (void)n_in; (void)out_size;
    gru_lstm_pipe1<<<NB, 64>>>(
        (const float*)d_in[0],
        (const float*)d_in[1], (const float*)d_in[2],
        (const float*)d_in[3], (const float*)d_in[4],
        (const float*)d_in[5], (const float*)d_in[6],
        (const float*)d_in[7], (const float*)d_in[8],
        (const float*)d_in[9], (const float*)d_in[10],
        (float*)d_out);
}